// round 15
// baseline (speedup 1.0000x reference)
#include <cuda_runtime.h>
#include <cuda_pipeline.h>
#include <math.h>

// SpectralEMA.  state_t = a*|state_{t-1}|*unit(x_t) + (1-rho)*x_t
//             = x_t * z_t / w_t,  z_t = a*m_{t-1} + omr*w_t,  m_t = |z_t|
// Real a (theta=0): m_t = rho*m_{t-1} + omr*w_t  -> affine scan; segments
// compose: m_out = rho^L * m_in + C_seg.
//
// Phase 1 (EXPERIMENT vs R8 baseline): cp.async pipelined loads.
//   2-stage x 4-step smem pipeline, 8B cp.async per (thread,step,array).
//   Each thread copies and consumes ONLY its own smem slots -> per-thread
//   __pipeline_wait_prior, no __syncthreads. Register prefetch buffers
//   (16 regs) are gone -> ~28 regs; a full 16KB stage is in flight per
//   block. Tests whether 6.9 TB/s was a per-warp LDG limit (win) or the
//   LTS/DRAM path cap (neutral).
// Phase 2: R8's exact proven kernel.

#define G   16
#define SPS 4                 // steps per pipeline stage
#define MAX_BF (32 * 4096)

__device__ float  g_C[G * MAX_BF];
__device__ float2 g_lx[MAX_BF];   // x at s = S-1 per chain

__device__ __forceinline__ float sigmoidf_(float x) {
    return 1.0f / (1.0f + expf(-x));
}

// |v| via single MUFU.RSQ
__device__ __forceinline__ float mag_(float vr, float vi) {
    float v2 = fmaxf(fmaf(vr, vr, vi * vi), 1e-37f);
    return v2 * rsqrtf(v2);
}

// x^e, integer e >= 0, by squaring (no MUFU)
__device__ __forceinline__ float powi_(float x, int e) {
    float r = 1.0f;
    while (e) {
        if (e & 1) r *= x;
        x *= x;
        e >>= 1;
    }
    return r;
}

// ---------------- Phase 1: cp.async pipelined segment scan ----------------
__global__ __launch_bounds__(256)
void phase1_kernel(const float* __restrict__ fr, const float* __restrict__ fi,
                   const float* __restrict__ ir, const float* __restrict__ ii,
                   const float* __restrict__ rho_logit,
                   int S, int F, int L)
{
    __shared__ float2 s_r[2][SPS][256];
    __shared__ float2 s_i[2][SPS][256];

    int F2 = F >> 1;
    int f2 = blockIdx.x * blockDim.x + threadIdx.x;
    if (f2 >= F2) return;
    int b   = blockIdx.y;
    int g   = blockIdx.z;
    int tid = threadIdx.x;

    float2 rl  = __ldg((const float2*)rho_logit + f2);
    float rho0 = sigmoidf_(rl.x), rho1 = sigmoidf_(rl.y);
    float om0  = 1.0f - rho0,     om1  = 1.0f - rho1;

    // Segment 0 seeds with m0=|init| -> its C becomes rho^L*m0 + C0.
    float C0 = 0.0f, C1 = 0.0f;
    if (g == 0) {
        size_t bfh = (size_t)b * (size_t)F2 + (size_t)f2;
        float2 s0 = __ldg((const float2*)ir + bfh);
        float2 s1 = __ldg((const float2*)ii + bfh);
        C0 = mag_(s0.x, s1.x);
        C1 = mag_(s0.y, s1.y);
    }

    size_t base = ((size_t)b * (size_t)S + (size_t)g * (size_t)L) * (size_t)F
                + (size_t)(f2 << 1);
    const float2* pr  = (const float2*)(fr + base);
    const float2* pim = (const float2*)(fi + base);
    size_t st = (size_t)F2;              // float2 stride per step

    int nstg = L / SPS;                  // 8 stages of 4 steps for L=32

    // prologue: fill both stage buffers
#pragma unroll
    for (int k = 0; k < SPS; ++k) {
        __pipeline_memcpy_async(&s_r[0][k][tid], pr  + (size_t)k * st, 8);
        __pipeline_memcpy_async(&s_i[0][k][tid], pim + (size_t)k * st, 8);
    }
    __pipeline_commit();
#pragma unroll
    for (int k = 0; k < SPS; ++k) {
        __pipeline_memcpy_async(&s_r[1][k][tid], pr  + (size_t)(SPS + k) * st, 8);
        __pipeline_memcpy_async(&s_i[1][k][tid], pim + (size_t)(SPS + k) * st, 8);
    }
    __pipeline_commit();

    float2 lxr = make_float2(0.f, 0.f), lxi = make_float2(0.f, 0.f);

#pragma unroll 1
    for (int sj = 0; sj < nstg; ++sj) {
        __pipeline_wait_prior(1);        // oldest group complete (own slots)
        int buf = sj & 1;
#pragma unroll
        for (int k = 0; k < SPS; ++k) {
            float2 xr = s_r[buf][k][tid];
            float2 xi = s_i[buf][k][tid];
            float wa = mag_(xr.x, xi.x);
            float wb = mag_(xr.y, xi.y);
            C0 = fmaf(rho0, C0, om0 * wa);
            C1 = fmaf(rho1, C1, om1 * wb);
            lxr = xr; lxi = xi;
        }
        if (sj + 2 < nstg) {
            size_t off = (size_t)(sj + 2) * SPS;
#pragma unroll
            for (int k = 0; k < SPS; ++k) {
                __pipeline_memcpy_async(&s_r[buf][k][tid], pr  + (off + k) * st, 8);
                __pipeline_memcpy_async(&s_i[buf][k][tid], pim + (off + k) * st, 8);
            }
        }
        __pipeline_commit();             // empty groups near the tail keep
                                         // wait_prior(1) semantics aligned
    }

    size_t bf0 = (size_t)b * (size_t)F + (size_t)(f2 << 1);
    *(float2*)(g_C + (size_t)g * MAX_BF + bf0) = make_float2(C0, C1);
    if (g == G - 1) {
        g_lx[bf0]     = make_float2(lxr.x, lxi.x);
        g_lx[bf0 + 1] = make_float2(lxr.y, lxi.y);
    }
}

// ---------------- Phase 2: combine segments, write output (R8) ----------------
__global__ __launch_bounds__(256)
void phase2_kernel(const float* __restrict__ fr, const float* __restrict__ fi,
                   const float* __restrict__ ir, const float* __restrict__ ii,
                   const float* __restrict__ rho_logit,
                   const float* __restrict__ theta_raw,
                   float2* __restrict__ out, int S, int F, int L)
{
    int f = blockIdx.x * blockDim.x + threadIdx.x;
    if (f >= F) return;
    int b = blockIdx.y;
    size_t bf = (size_t)b * (size_t)F + (size_t)f;

    float thw = __ldg(theta_raw + f);
    float rho = sigmoidf_(__ldg(rho_logit + f));

    if (thw == 0.0f) {
        float c[G];
#pragma unroll
        for (int g = 0; g < G; ++g)
            c[g] = __ldg(g_C + (size_t)g * MAX_BF + bf);
        float2 lx = g_lx[bf];

        float D = powi_(rho, L);
        float m = c[0];
#pragma unroll
        for (int g = 1; g < G; ++g)
            m = fmaf(D, m, c[g]);
        float w2 = fmaxf(fmaf(lx.x, lx.x, lx.y * lx.y), 1e-37f);
        float s  = m * rsqrtf(w2);
        out[bf] = make_float2(lx.x * s, lx.y * s);
    } else {
        float th = 3.14159265358979323846f * tanhf(thw);
        float ss, sc;
        sincosf(th, &ss, &sc);
        float ar = rho * sc, ai = rho * ss, omr = 1.0f - rho;
        float m = mag_(__ldg(ir + bf), __ldg(ii + bf));
        const float* p  = fr + (size_t)b * (size_t)S * (size_t)F + f;
        const float* pi = fi + (size_t)b * (size_t)S * (size_t)F + f;
        float zr = 0.f, zi = 0.f, rinv = 1.f, lr = 0.f, li = 0.f;
        for (int s = 0; s < S; ++s) {
            float xr = __ldg(p), xi = __ldg(pi);
            p += F; pi += F;
            float x2 = fmaxf(fmaf(xr, xr, xi * xi), 1e-37f);
            float rv = rsqrtf(x2);
            float w  = x2 * rv;
            zr = fmaf(ar, m, omr * w);
            zi = ai * m;
            m = mag_(zr, zi);
            rinv = rv; lr = xr; li = xi;
        }
        out[bf] = make_float2((zr * lr - zi * li) * rinv,
                              fmaf(zr, li, zi * lr) * rinv);
    }
}

// ---------------- Monolithic fallback (unexpected shapes) ----------------
__global__ __launch_bounds__(256)
void mono_kernel(const float* __restrict__ fr, const float* __restrict__ fi,
                 const float* __restrict__ ir, const float* __restrict__ ii,
                 const float* __restrict__ rho_logit,
                 const float* __restrict__ theta_raw,
                 float2* __restrict__ out, int S, int F)
{
    int f = blockIdx.x * blockDim.x + threadIdx.x;
    if (f >= F) return;
    int b = blockIdx.y;
    size_t bf = (size_t)b * (size_t)F + (size_t)f;

    float rho = sigmoidf_(rho_logit[f]);
    float th  = 3.14159265358979323846f * tanhf(theta_raw[f]);
    float ss, sc;
    sincosf(th, &ss, &sc);
    float ar = rho * sc, ai = rho * ss, omr = 1.0f - rho;

    float m = mag_(ir[bf], ii[bf]);

    const float* pr  = fr + (size_t)b * (size_t)S * (size_t)F + f;
    const float* pim = fi + (size_t)b * (size_t)S * (size_t)F + f;
    float zr = 0.f, zi = 0.f, rinv = 1.f, lxr = 0.f, lxi = 0.f;
    for (int s = 0; s < S; ++s) {
        float xr = __ldcs(pr), xi = __ldcs(pim);
        pr += F; pim += F;
        float x2 = fmaxf(fmaf(xr, xr, xi * xi), 1e-37f);
        float rv = rsqrtf(x2);
        float w  = x2 * rv;
        zr = fmaf(ar, m, omr * w);
        zi = ai * m;
        m = mag_(zr, zi);
        rinv = rv; lxr = xr; lxi = xi;
    }
    out[bf] = make_float2((zr * lxr - zi * lxi) * rinv,
                          fmaf(zr, lxi, zi * lxr) * rinv);
}

extern "C" void kernel_launch(void* const* d_in, const int* in_sizes, int n_in,
                              void* d_out, int out_size)
{
    const float* fr = (const float*)d_in[0];
    const float* fi = (const float*)d_in[1];
    const float* ir = (const float*)d_in[2];
    const float* ii = (const float*)d_in[3];
    const float* rl = (const float*)d_in[4];
    const float* tr = (const float*)d_in[5];

    int F  = in_sizes[4];
    int BF = in_sizes[2];
    int B  = BF / F;
    int S  = in_sizes[0] / BF;

    dim3 block(256);

    bool fast = (BF <= MAX_BF) && (F % 512 == 0) &&
                (S % (G * SPS) == 0) && ((S / G) % SPS == 0) && (S / G >= 2 * SPS);
    if (fast) {
        int L  = S / G;
        int F2 = F / 2;
        dim3 grid1(F2 / 256, B, G);
        phase1_kernel<<<grid1, block>>>(fr, fi, ir, ii, rl, S, F, L);
        dim3 grid2((F + 255) / 256, B);
        phase2_kernel<<<grid2, block>>>(fr, fi, ir, ii, rl, tr,
                                        (float2*)d_out, S, F, L);
    } else {
        dim3 grid((F + 255) / 256, B);
        mono_kernel<<<grid, block>>>(fr, fi, ir, ii, rl, tr,
                                     (float2*)d_out, S, F);
    }
}

// round 16
// speedup vs baseline: 1.2516x; 1.2516x over previous
#include <cuda_runtime.h>
#include <math.h>

// SpectralEMA.  state_t = a*|state_{t-1}|*unit(x_t) + (1-rho)*x_t
//             = x_t * z_t / w_t,  z_t = a*m_{t-1} + omr*w_t,  m_t = |z_t|
// Real a (theta=0): m_t = rho*m_{t-1} + omr*w_t  -> affine scan; segments
// compose: m_out = rho^L * m_in + C_seg.
// Phase 1 (FINAL, proven across R3/R5/R8/R14; every perturbation measured
//   worse): float2 = 2 feat/thread, UNR=4 register double-buffer, G=16,
//   4096 blocks, 40 regs, 6 blocks/SM, ~6.9 TB/s.
// Phase 2: all 19 loads hoisted ABOVE the theta branch (one DRAM round
//   trip instead of two serialized ones), then combine + reconstruct.

#define G   16
#define UNR 4
#define MAX_BF (32 * 4096)

__device__ float  g_C[G * MAX_BF];
__device__ float2 g_lx[MAX_BF];   // x at s = S-1 per chain

__device__ __forceinline__ float sigmoidf_(float x) {
    return 1.0f / (1.0f + expf(-x));
}

// |v| via single MUFU.RSQ
__device__ __forceinline__ float mag_(float vr, float vi) {
    float v2 = fmaxf(fmaf(vr, vr, vi * vi), 1e-37f);
    return v2 * rsqrtf(v2);
}

// x^e, integer e >= 0, by squaring (no MUFU)
__device__ __forceinline__ float powi_(float x, int e) {
    float r = 1.0f;
    while (e) {
        if (e & 1) r *= x;
        x *= x;
        e >>= 1;
    }
    return r;
}

// ---------------- Phase 1: per-segment affine coefficient C ----------------
__global__ __launch_bounds__(256)
void phase1_kernel(const float* __restrict__ fr, const float* __restrict__ fi,
                   const float* __restrict__ ir, const float* __restrict__ ii,
                   const float* __restrict__ rho_logit,
                   int S, int F, int L)
{
    int F2 = F >> 1;
    int f2 = blockIdx.x * blockDim.x + threadIdx.x;
    if (f2 >= F2) return;
    int b = blockIdx.y;
    int g = blockIdx.z;

    float2 rl  = __ldg((const float2*)rho_logit + f2);
    float rho0 = sigmoidf_(rl.x), rho1 = sigmoidf_(rl.y);
    float om0  = 1.0f - rho0,     om1  = 1.0f - rho1;

    // Segment 0 seeds with m0=|init| -> its C becomes rho^L*m0 + C0.
    float C0 = 0.0f, C1 = 0.0f;
    if (g == 0) {
        size_t bfh = (size_t)b * (size_t)F2 + (size_t)f2;
        float2 s0 = __ldg((const float2*)ir + bfh);
        float2 s1 = __ldg((const float2*)ii + bfh);
        C0 = mag_(s0.x, s1.x);
        C1 = mag_(s0.y, s1.y);
    }

    size_t base = ((size_t)b * (size_t)S + (size_t)g * (size_t)L) * (size_t)F
                + (size_t)(f2 << 1);
    const float2* pr  = (const float2*)(fr + base);
    const float2* pim = (const float2*)(fi + base);
    size_t st = (size_t)F2;              // float2 stride per step

    float2 lxr = make_float2(0.f, 0.f), lxi = make_float2(0.f, 0.f);

    int nch = L / UNR;
    float2 cr[UNR], ci[UNR];
#pragma unroll
    for (int k = 0; k < UNR; ++k) {
        cr[k] = __ldcs(pr  + (size_t)k * st);
        ci[k] = __ldcs(pim + (size_t)k * st);
    }
    pr  += (size_t)UNR * st;
    pim += (size_t)UNR * st;

#pragma unroll 1
    for (int j = 0; j < nch; ++j) {
        float2 nr[UNR], ni[UNR];
        if (j + 1 < nch) {
#pragma unroll
            for (int k = 0; k < UNR; ++k) {
                nr[k] = __ldcs(pr  + (size_t)k * st);
                ni[k] = __ldcs(pim + (size_t)k * st);
            }
            pr  += (size_t)UNR * st;
            pim += (size_t)UNR * st;
        }
#pragma unroll
        for (int k = 0; k < UNR; ++k) {
            float wa = mag_(cr[k].x, ci[k].x);
            float wb = mag_(cr[k].y, ci[k].y);
            C0 = fmaf(rho0, C0, om0 * wa);
            C1 = fmaf(rho1, C1, om1 * wb);
            lxr = cr[k]; lxi = ci[k];
        }
#pragma unroll
        for (int k = 0; k < UNR; ++k) { cr[k] = nr[k]; ci[k] = ni[k]; }
    }

    size_t bf0 = (size_t)b * (size_t)F + (size_t)(f2 << 1);
    *(float2*)(g_C + (size_t)g * MAX_BF + bf0) = make_float2(C0, C1);
    if (g == G - 1) {
        g_lx[bf0]     = make_float2(lxr.x, lxi.x);
        g_lx[bf0 + 1] = make_float2(lxr.y, lxi.y);
    }
}

// ---------------- Phase 2: combine segments, write output ----------------
__global__ __launch_bounds__(256)
void phase2_kernel(const float* __restrict__ fr, const float* __restrict__ fi,
                   const float* __restrict__ ir, const float* __restrict__ ii,
                   const float* __restrict__ rho_logit,
                   const float* __restrict__ theta_raw,
                   float2* __restrict__ out, int S, int F, int L)
{
    int f = blockIdx.x * blockDim.x + threadIdx.x;
    if (f >= F) return;
    int b = blockIdx.y;
    size_t bf = (size_t)b * (size_t)F + (size_t)f;

    // ---- hoisted load batch: ONE DRAM round trip, max MLP (19 loads) ----
    float c[G];
#pragma unroll
    for (int g = 0; g < G; ++g)
        c[g] = __ldg(g_C + (size_t)g * MAX_BF + bf);
    float2 lx  = __ldg(&g_lx[bf]);
    float  thw = __ldg(theta_raw + f);
    float  rho = sigmoidf_(__ldg(rho_logit + f));
    float  D   = powi_(rho, L);   // overlaps with outstanding loads

    if (thw == 0.0f) {
        float m = c[0];            // init already folded into segment 0
#pragma unroll
        for (int g = 1; g < G; ++g)
            m = fmaf(D, m, c[g]);
        // m == z_last (real, >= 0).  out = x_last * m / |x_last|
        float w2 = fmaxf(fmaf(lx.x, lx.x, lx.y * lx.y), 1e-37f);
        float s  = m * rsqrtf(w2);
        out[bf] = make_float2(lx.x * s, lx.y * s);
    } else {
        // general complex-a path (not taken for this dataset): full rescan
        float th = 3.14159265358979323846f * tanhf(thw);
        float ss, sc;
        sincosf(th, &ss, &sc);
        float ar = rho * sc, ai = rho * ss, omr = 1.0f - rho;
        float m = mag_(__ldg(ir + bf), __ldg(ii + bf));
        const float* p  = fr + (size_t)b * (size_t)S * (size_t)F + f;
        const float* pi = fi + (size_t)b * (size_t)S * (size_t)F + f;
        float zr = 0.f, zi = 0.f, rinv = 1.f, lr = 0.f, li = 0.f;
        for (int s = 0; s < S; ++s) {
            float xr = __ldg(p), xi = __ldg(pi);
            p += F; pi += F;
            float x2 = fmaxf(fmaf(xr, xr, xi * xi), 1e-37f);
            float rv = rsqrtf(x2);
            float w  = x2 * rv;
            zr = fmaf(ar, m, omr * w);
            zi = ai * m;
            m = mag_(zr, zi);
            rinv = rv; lr = xr; li = xi;
        }
        out[bf] = make_float2((zr * lr - zi * li) * rinv,
                              fmaf(zr, li, zi * lr) * rinv);
    }
}

// ---------------- Monolithic fallback (unexpected shapes) ----------------
__global__ __launch_bounds__(256)
void mono_kernel(const float* __restrict__ fr, const float* __restrict__ fi,
                 const float* __restrict__ ir, const float* __restrict__ ii,
                 const float* __restrict__ rho_logit,
                 const float* __restrict__ theta_raw,
                 float2* __restrict__ out, int S, int F)
{
    int f = blockIdx.x * blockDim.x + threadIdx.x;
    if (f >= F) return;
    int b = blockIdx.y;
    size_t bf = (size_t)b * (size_t)F + (size_t)f;

    float rho = sigmoidf_(rho_logit[f]);
    float th  = 3.14159265358979323846f * tanhf(theta_raw[f]);
    float ss, sc;
    sincosf(th, &ss, &sc);
    float ar = rho * sc, ai = rho * ss, omr = 1.0f - rho;

    float m = mag_(ir[bf], ii[bf]);

    const float* pr  = fr + (size_t)b * (size_t)S * (size_t)F + f;
    const float* pim = fi + (size_t)b * (size_t)S * (size_t)F + f;
    float zr = 0.f, zi = 0.f, rinv = 1.f, lxr = 0.f, lxi = 0.f;
    for (int s = 0; s < S; ++s) {
        float xr = __ldcs(pr), xi = __ldcs(pim);
        pr += F; pim += F;
        float x2 = fmaxf(fmaf(xr, xr, xi * xi), 1e-37f);
        float rv = rsqrtf(x2);
        float w  = x2 * rv;
        zr = fmaf(ar, m, omr * w);
        zi = ai * m;
        m = mag_(zr, zi);
        rinv = rv; lxr = xr; lxi = xi;
    }
    out[bf] = make_float2((zr * lxr - zi * lxi) * rinv,
                          fmaf(zr, lxi, zi * lxr) * rinv);
}

extern "C" void kernel_launch(void* const* d_in, const int* in_sizes, int n_in,
                              void* d_out, int out_size)
{
    const float* fr = (const float*)d_in[0];
    const float* fi = (const float*)d_in[1];
    const float* ir = (const float*)d_in[2];
    const float* ii = (const float*)d_in[3];
    const float* rl = (const float*)d_in[4];
    const float* tr = (const float*)d_in[5];

    int F  = in_sizes[4];
    int BF = in_sizes[2];
    int B  = BF / F;
    int S  = in_sizes[0] / BF;

    dim3 block(256);

    bool fast = (BF <= MAX_BF) && (F % 512 == 0) && (S % (G * UNR) == 0);
    if (fast) {
        int L  = S / G;
        int F2 = F / 2;
        dim3 grid1(F2 / 256, B, G);
        phase1_kernel<<<grid1, block>>>(fr, fi, ir, ii, rl, S, F, L);
        dim3 grid2((F + 255) / 256, B);
        phase2_kernel<<<grid2, block>>>(fr, fi, ir, ii, rl, tr,
                                        (float2*)d_out, S, F, L);
    } else {
        dim3 grid((F + 255) / 256, B);
        mono_kernel<<<grid, block>>>(fr, fi, ir, ii, rl, tr,
                                     (float2*)d_out, S, F);
    }
}